// round 15
// baseline (speedup 1.0000x reference)
#include <cuda_runtime.h>
#include <cuda_bf16.h>
#include <cstdint>

// ---------------------------------------------------------------------------
// Problem constants
// ---------------------------------------------------------------------------
#define T_STEPS   512
#define IN_DIM    1024
#define DGRID     256
#define OUT_DIM   128
#define NPIX      (DGRID * DGRID)          // 65536
#define KTOT      (2 * NPIX)               // 131072  (V,S channels)

// GEMM tiling / split-K  (R4-measured-best shape: static 160-CTA grid)
#define BM        128
#define BN        128
#define BK        32
#define NSLICES   16                       // slices per segment over KTOT
#define GSLICE    (KTOT / NSLICES)         // 8192
#define KITERS    (GSLICE / BK)            // 256
// segments: 0 = Ahi*Whi (16 slices), 1 = Ahi*Wlo (16), 2 = Alo*Whi (8: V region only)
#define NSEG_TOT  40

// ---------------------------------------------------------------------------
// Device scratch (static allocations only)
// ---------------------------------------------------------------------------
__device__ int            g_perm[IN_DIM];
__device__ float          g_wval[IN_DIM];
__device__ float          g_tanhu[T_STEPS * IN_DIM];
// tagged S words: [parity][row][chunk] = (tag<<32) | ballot(32 px)
__device__ unsigned long long g_S64[2][DGRID][8];
__device__ __nv_bfloat16  g_Ahi[(size_t)T_STEPS * KTOT];   // [t][ch][pix]  134MB
__device__ __nv_bfloat16  g_Alo[(size_t)T_STEPS * KTOT];   // S half stays 0
__device__ __nv_bfloat16  g_Whi[(size_t)OUT_DIM * KTOT];   // native W layout
__device__ __nv_bfloat16  g_Wlo[(size_t)OUT_DIM * KTOT];
__device__ float          g_part[(size_t)NSEG_TOT * T_STEPS * OUT_DIM];

// ---------------------------------------------------------------------------
// PTX helpers (plain sm_70/80+ features -> safe for .target sm_103)
// ---------------------------------------------------------------------------
__device__ __forceinline__ uint32_t smem_u32(const void* p) {
    return (uint32_t)__cvta_generic_to_shared(p);
}
__device__ __forceinline__ void cp_async16(uint32_t saddr, const void* gaddr) {
    asm volatile("cp.async.cg.shared.global [%0], [%1], 16;" :: "r"(saddr), "l"(gaddr));
}
__device__ __forceinline__ void cp_commit() {
    asm volatile("cp.async.commit_group;" ::: "memory");
}
__device__ __forceinline__ void cp_wait1() {
    asm volatile("cp.async.wait_group 1;" ::: "memory");
}
__device__ __forceinline__ void cp_wait0() {
    asm volatile("cp.async.wait_group 0;" ::: "memory");
}
__device__ __forceinline__ void ldsm_x4(uint32_t& r0, uint32_t& r1, uint32_t& r2,
                                        uint32_t& r3, uint32_t addr) {
    asm volatile("ldmatrix.sync.aligned.m8n8.x4.shared.b16 {%0,%1,%2,%3}, [%4];"
                 : "=r"(r0), "=r"(r1), "=r"(r2), "=r"(r3) : "r"(addr));
}
__device__ __forceinline__ void mma_bf16(float* d, const uint32_t* a, const uint32_t* b) {
    asm volatile(
        "mma.sync.aligned.m16n8k16.row.col.f32.bf16.bf16.f32 "
        "{%0,%1,%2,%3}, {%4,%5,%6,%7}, {%8,%9}, {%0,%1,%2,%3};"
        : "+f"(d[0]), "+f"(d[1]), "+f"(d[2]), "+f"(d[3])
        : "r"(a[0]), "r"(a[1]), "r"(a[2]), "r"(a[3]), "r"(b[0]), "r"(b[1]));
}
// GPU-scope relaxed atomics (the R7-proven scan sync; NOT volatile/SYS)
__device__ __forceinline__ unsigned long long ld_relaxed_u64(const unsigned long long* p) {
    unsigned long long v;
    asm volatile("ld.relaxed.gpu.global.u64 %0, [%1];" : "=l"(v) : "l"(p) : "memory");
    return v;
}
__device__ __forceinline__ void st_relaxed_u64(unsigned long long* p, unsigned long long v) {
    asm volatile("st.relaxed.gpu.global.u64 [%0], %1;" :: "l"(p), "l"(v) : "memory");
}

// ---------------------------------------------------------------------------
// Kernel 0: reset sync state (every graph replay)
// ---------------------------------------------------------------------------
__global__ void init_kernel() {
    int i = blockIdx.x * blockDim.x + threadIdx.x;
    if (i < 2 * DGRID * 8) ((unsigned long long*)g_S64)[i] = 0ull;
}

// ---------------------------------------------------------------------------
// Kernel 1: discover permutation from the permuted-identity embed matrix
// ---------------------------------------------------------------------------
__global__ void perm_kernel(const float* __restrict__ We) {
    int row = blockIdx.x;
    for (int j = threadIdx.x; j < IN_DIM; j += blockDim.x) {
        float w = We[row * IN_DIM + j];
        if (fabsf(w) > 0.5f) { g_perm[row] = j; g_wval[row] = w; }
    }
}

// ---------------------------------------------------------------------------
// Kernel 2: tanhu[t, ci] = tanh(mask_coarse[ci] * X[t, perm[ci]])
// ---------------------------------------------------------------------------
__global__ void tanhu_kernel(const float* __restrict__ X,
                             const float* __restrict__ mc) {
    int idx = blockIdx.x * blockDim.x + threadIdx.x;
    if (idx >= T_STEPS * IN_DIM) return;
    int t  = idx >> 10;
    int ci = idx & 1023;
    float v = X[(t << 10) + g_perm[ci]] * g_wval[ci];
    g_tanhu[idx] = tanhf(__fmul_rn(mc[ci], v));
}

// ---------------------------------------------------------------------------
// Kernel 3: persistent reservoir scan = R4 code with ONE change: the tagged
// word poll/publish uses GPU-scope relaxed atomics instead of volatile
// (volatile compiles to STRONG.SYS; relaxed.gpu measured -90us on the scan).
// Output layout/stores byte-identical to R4 ([t][ch][pix], plain 2B stores).
// ---------------------------------------------------------------------------
__global__ void __launch_bounds__(512, 1)
scan_kernel(const float* __restrict__ mask_fine) {
    const int b    = blockIdx.x;
    const int tid  = threadIdx.x;
    const int dy   = tid >> 8;
    const int x    = tid & 255;
    const int y    = (b << 1) + dy;
    const int ci   = ((y >> 3) << 5) + (x >> 3);
    const float mf = mask_fine[(y << 8) + x];
    const int w    = tid >> 5;           // warp 0..15
    const int lane = tid & 31;

    __shared__ unsigned sS[2][18][8];    // [parity][halo row k][chunk]

    const int b5 = (x - 2) & 255, w5 = b5 >> 5, o5 = b5 & 31, w5b = (w5 + 1) & 7;
    const int b9 = (x - 8) & 255, w9 = b9 >> 5, o9 = b9 & 31, w9b = (w9 + 1) & 7;
    const int krow = 8 + dy;

    // halo assignment: warp w<8 -> k=w (rows y0-8..y0-1); w>=8 -> k=w+2 (y0+2..y0+9)
    int hk, hrow;
    if (w < 8) { hk = w;     hrow = ((b << 1) - 8 + w) & 255; }
    else       { hk = w + 2; hrow = ((b << 1) - 6 + w) & 255; }
    unsigned long long* hp0 = &g_S64[0][hrow][lane & 7];
    unsigned long long* hp1 = &g_S64[1][hrow][lane & 7];

    // prefill own rows of smem buffer 0 with S(-1)=0
    if (lane == 0) sS[0][8 + (w >> 3)][w & 7] = 0u;

    float V = 0.0f;
    const int pix = (y << 8) + x;

    for (int t = 0; t < T_STEPS; ++t) {
        float u  = __fmul_rn(mf, __ldg(&g_tanhu[(t << 10) + ci]));
        float Vd = __fadd_rn(__fmul_rn(0.9f, V), __fmul_rn(0.5f, u));

        const int sb = t & 1;
        // halo: poll tagged word (tag>=t) and stage payload; one L2 RT total
        if (lane < 8) {
            unsigned long long* p = (t & 1) ? hp0 : hp1;   // parity (t-1)&1
            unsigned long long v = ld_relaxed_u64(p);
            while ((unsigned)(v >> 32) < (unsigned)t) v = ld_relaxed_u64(p);
            sS[sb][hk][lane] = (unsigned)v;
        }
        __syncthreads();   // the ONLY barrier per step

        int n5 = 0;
#pragma unroll
        for (int d = -2; d <= 2; ++d) {
            unsigned v = __funnelshift_r(sS[sb][krow + d][w5], sS[sb][krow + d][w5b], o5);
            n5 += __popc(v & 0x1Fu);
        }
        int n9 = 0;
#pragma unroll
        for (int d = -8; d <= 8; d += 2) {
            unsigned v = __funnelshift_r(sS[sb][krow + d][w9], sS[sb][krow + d][w9b], o9);
            n9 += __popc(v & 0x15555u);
        }
        float c5  = __fmul_rn((float)n5, 1.0f / 25.0f);
        float c9  = __fmul_rn((float)n9, 1.0f / 81.0f);
        float lat = __fadd_rn(c5, __fmul_rn(-0.5f, c9));

        float Vn = Vd;
        if (Vd >= 0.1f)
            Vn = __fadd_rn(__fadd_rn(Vd, __fmul_rn(0.5f, u)), lat);
        Vn = fminf(Vn, 1.0f);
        bool Sb = (Vn > 0.75f);
        if (Sb) Vn = 0.0f;
        V = Vn;

        // publish: single tagged 8-byte relaxed GPU-scope store
        unsigned ball = __ballot_sync(0xffffffffu, Sb);
        if (lane == 0) {
            unsigned long long pk =
                ((unsigned long long)(unsigned)(t + 1) << 32) | (unsigned long long)ball;
            st_relaxed_u64(&g_S64[t & 1][y][w & 7], pk);
            sS[sb ^ 1][8 + dy][w & 7] = ball;   // own rows for next step
        }

        // stream split-precision outputs (R4 layout + stores, unchanged)
        __nv_bfloat16 vh = __float2bfloat16(Vn);
        float vlo = Vn - __bfloat162float(vh);
        size_t obase = (size_t)t * KTOT + pix;
        g_Ahi[obase]        = vh;
        g_Ahi[obase + NPIX] = Sb ? __float2bfloat16(1.0f) : __float2bfloat16(0.0f);
        g_Alo[obase]        = __float2bfloat16(vlo);   // S-lo region never written: stays 0
    }
}

// ---------------------------------------------------------------------------
// Kernel 2b: split W into bf16 hi/lo (R4 version: 8 elems/thread, native
// [o][ch][pix] layout, 16B stores)
// ---------------------------------------------------------------------------
__global__ void wsplit_kernel(const float* __restrict__ W) {
    int idx = blockIdx.x * blockDim.x + threadIdx.x;     // 8 elems each
    if (idx >= OUT_DIM * KTOT / 8) return;
    const float4* W4 = (const float4*)W;
    float4 a = W4[idx * 2];
    float4 b = W4[idx * 2 + 1];
    float f[8] = {a.x, a.y, a.z, a.w, b.x, b.y, b.z, b.w};
    __nv_bfloat16 hi[8], lo[8];
#pragma unroll
    for (int i = 0; i < 8; ++i) {
        hi[i] = __float2bfloat16(f[i]);
        lo[i] = __float2bfloat16(f[i] - __bfloat162float(hi[i]));
    }
    ((uint4*)g_Whi)[idx] = *(uint4*)hi;
    ((uint4*)g_Wlo)[idx] = *(uint4*)lo;
}

// ---------------------------------------------------------------------------
// Kernel 4: bf16 HMMA split-K GEMM — EXACT R4 version (measured ~210us).
// grid = (4 M-tiles, 40 segments/slices) = 160 CTAs, BM=128, BN=128, BK=32,
// 256 thr, warp tile 32x64, double-buffered cp.async, padded smem.
// ---------------------------------------------------------------------------
__global__ void __launch_bounds__(256)
mma_gemm_kernel() {
    __shared__ __nv_bfloat16 sA[2][BM][BK + 8];
    __shared__ __nv_bfloat16 sB[2][BN][BK + 8];

    const int mt = blockIdx.x;           // 0..3
    const int s  = blockIdx.y;           // 0..39
    int seg, slice;
    if (s < 16)      { seg = 0; slice = s; }
    else if (s < 32) { seg = 1; slice = s - 16; }
    else             { seg = 2; slice = s - 32; }    // only V-region slices
    const size_t k0 = (size_t)slice * GSLICE;

    const __nv_bfloat16* Abase = (seg == 2) ? g_Alo : g_Ahi;
    const __nv_bfloat16* Bbase = (seg == 1) ? g_Wlo : g_Whi;

    const int tid  = threadIdx.x;
    const int wid  = tid >> 5;
    const int lane = tid & 31;
    const int wm   = wid >> 1;           // 0..3  -> rows wm*32
    const int wn   = wid & 1;            // 0..1  -> cols wn*64

    const int lrow = tid >> 1;
    const int lch  = (tid & 1) << 1;     // chunk index 0 or 2 (each 8 bf16)
    const __nv_bfloat16* gA = Abase + (size_t)(mt * BM + lrow) * KTOT + k0 + lch * 8;
    const __nv_bfloat16* gB = Bbase + (size_t)lrow * KTOT + k0 + lch * 8;
    const uint32_t sA0 = smem_u32(&sA[0][0][0]);
    const uint32_t sB0 = smem_u32(&sB[0][0][0]);
    const uint32_t bufBytes = (uint32_t)BM * (BK + 8) * 2;
    const uint32_t rowOffA = ((uint32_t)lrow * (BK + 8) + lch * 8) * 2;
    const uint32_t rowOffB = rowOffA;

    const int aRow = wm * 32 + (lane & 15);
    const int aK   = (lane >> 4) << 3;
    const int bRow = wn * 64 + (lane & 7) + ((lane >> 4) << 3);
    const int bK   = ((lane >> 3) & 1) << 3;

    float d[2][8][4];
#pragma unroll
    for (int mi = 0; mi < 2; ++mi)
#pragma unroll
        for (int ni = 0; ni < 8; ++ni)
#pragma unroll
            for (int r = 0; r < 4; ++r) d[mi][ni][r] = 0.0f;

    {
        cp_async16(sA0 + rowOffA, gA);
        cp_async16(sA0 + rowOffA + 16, gA + 8);
        cp_async16(sB0 + rowOffB, gB);
        cp_async16(sB0 + rowOffB + 16, gB + 8);
        cp_commit();
    }

    for (int it = 0; it < KITERS; ++it) {
        const int cb = it & 1;
        if (it + 1 < KITERS) {
            const int nb = (it + 1) & 1;
            const __nv_bfloat16* ga = gA + (size_t)(it + 1) * BK;
            const __nv_bfloat16* gb = gB + (size_t)(it + 1) * BK;
            cp_async16(sA0 + nb * bufBytes + rowOffA, ga);
            cp_async16(sA0 + nb * bufBytes + rowOffA + 16, ga + 8);
            cp_async16(sB0 + nb * bufBytes + rowOffB, gb);
            cp_async16(sB0 + nb * bufBytes + rowOffB + 16, gb + 8);
            cp_commit();
            cp_wait1();
        } else {
            cp_wait0();
        }
        __syncthreads();

#pragma unroll
        for (int ks = 0; ks < 2; ++ks) {
            const int kc = ks * 16;
            uint32_t a[2][4], bf[4][4];
#pragma unroll
            for (int mi = 0; mi < 2; ++mi) {
                uint32_t addr = sA0 + cb * bufBytes +
                    ((uint32_t)(aRow + mi * 16) * (BK + 8) + kc + aK) * 2;
                ldsm_x4(a[mi][0], a[mi][1], a[mi][2], a[mi][3], addr);
            }
#pragma unroll
            for (int g = 0; g < 4; ++g) {
                uint32_t addr = sB0 + cb * bufBytes +
                    ((uint32_t)(bRow + g * 16) * (BK + 8) + kc + bK) * 2;
                ldsm_x4(bf[g][0], bf[g][1], bf[g][2], bf[g][3], addr);
            }
#pragma unroll
            for (int mi = 0; mi < 2; ++mi)
#pragma unroll
                for (int g = 0; g < 4; ++g) {
                    mma_bf16(d[mi][g * 2 + 0], a[mi], &bf[g][0]);
                    mma_bf16(d[mi][g * 2 + 1], a[mi], &bf[g][2]);
                }
        }
        __syncthreads();
    }

#pragma unroll
    for (int mi = 0; mi < 2; ++mi) {
        const int m0 = mt * BM + wm * 32 + mi * 16 + (lane >> 2);
#pragma unroll
        for (int ni = 0; ni < 8; ++ni) {
            const int col = wn * 64 + ni * 8 + (lane & 3) * 2;
            float2 v01 = make_float2(d[mi][ni][0], d[mi][ni][1]);
            float2 v23 = make_float2(d[mi][ni][2], d[mi][ni][3]);
            *reinterpret_cast<float2*>(
                &g_part[((size_t)s * T_STEPS + m0) * OUT_DIM + col]) = v01;
            *reinterpret_cast<float2*>(
                &g_part[((size_t)s * T_STEPS + m0 + 8) * OUT_DIM + col]) = v23;
        }
    }
}

// ---------------------------------------------------------------------------
// Kernel 5: deterministic split-K reduction + bias
// ---------------------------------------------------------------------------
__global__ void reduce_kernel(const float* __restrict__ b_out,
                              float* __restrict__ out) {
    int i = blockIdx.x * blockDim.x + threadIdx.x;
    if (i >= T_STEPS * OUT_DIM) return;
    int o = i & (OUT_DIM - 1);
    float sum = 0.0f;
#pragma unroll 8
    for (int ks = 0; ks < NSEG_TOT; ++ks)
        sum += g_part[(size_t)ks * (T_STEPS * OUT_DIM) + i];
    out[i] = sum + b_out[o];
}

// ---------------------------------------------------------------------------
// Launch: sequential default stream, R4 order; scan is launch #4 for ncu.
// ---------------------------------------------------------------------------
extern "C" void kernel_launch(void* const* d_in, const int* in_sizes, int n_in,
                              void* d_out, int out_size) {
    const float* X  = (const float*)d_in[0];   // [512,1024]
    const float* We = (const float*)d_in[1];   // [1024,1024]
    const float* mc = (const float*)d_in[2];   // [1,1,32,32]
    const float* mf = (const float*)d_in[3];   // [1,1,256,256]
    const float* W  = (const float*)d_in[4];   // [128,2,256,256]
    const float* bo = (const float*)d_in[5];   // [128]
    float* out = (float*)d_out;                // [512,128]

    init_kernel<<<16, 256>>>();
    perm_kernel<<<IN_DIM, 256>>>(We);
    tanhu_kernel<<<(T_STEPS * IN_DIM + 255) / 256, 256>>>(X, mc);
    scan_kernel<<<128, 512>>>(mf);
    wsplit_kernel<<<(OUT_DIM * KTOT / 8 + 255) / 256, 256>>>(W);
    dim3 ggrid(4, NSEG_TOT);
    mma_gemm_kernel<<<ggrid, 256>>>();
    reduce_kernel<<<(T_STEPS * OUT_DIM + 255) / 256, 256>>>(bo, out);
}